// round 1
// baseline (speedup 1.0000x reference)
#include <cuda_runtime.h>
#include <cstdint>
#include <math.h>

#define H      1024
#define H4     (H/4)          // 256 float4 per H row
#define H2     512
#define V      32000
#define WIN    129
#define WWIN   64
#define GATE4  (H * H4)       // float4 stride between gates: 1024*256

// ---------------- scratch (no allocation allowed) ----------------
__device__ float g_t1[H2];     // tanh(att_fc1 output)
__device__ float g_p;          // attention position
__device__ int   g_ws, g_we;   // window start / end
__device__ float g_scores[WIN];
__device__ float g_ctx[H];

// ---------------- helpers ----------------
__device__ __forceinline__ float dot4(float4 a, float4 b) {
    return fmaf(a.x, b.x, fmaf(a.y, b.y, fmaf(a.z, b.z, a.w * b.w)));
}
__device__ __forceinline__ float warpSum(float v) {
    #pragma unroll
    for (int o = 16; o > 0; o >>= 1) v += __shfl_xor_sync(0xffffffffu, v, o);
    return v;
}
__device__ __forceinline__ float warpMax(float v) {
    #pragma unroll
    for (int o = 16; o > 0; o >>= 1) v = fmaxf(v, __shfl_xor_sync(0xffffffffu, v, o));
    return v;
}
__device__ __forceinline__ float sigm(float x) { return 1.f / (1.f + expf(-x)); }

// ---------------- LSTM layer: one warp per output element j ----------------
// gates rows j, j+H, j+2H, j+3H of w_ih/w_hh; fused cell nonlinearity.
__global__ void lstm_kernel(const float* __restrict__ xbase,
                            const int*   __restrict__ widx,   // null for layer 1
                            const float* __restrict__ hprev,
                            const float* __restrict__ cprev,
                            const float* __restrict__ w_ih,
                            const float* __restrict__ w_hh,
                            const float* __restrict__ b_ih,
                            const float* __restrict__ b_hh,
                            float* __restrict__ h_out,
                            float* __restrict__ c_out)
{
    int j    = (blockIdx.x * blockDim.x + threadIdx.x) >> 5;   // 0..1023
    int lane = threadIdx.x & 31;
    const float* x = xbase + (widx ? (size_t)widx[0] * H : 0);
    const float4* x4  = (const float4*)x;
    const float4* h4  = (const float4*)hprev;
    const float4* wi  = (const float4*)w_ih + (size_t)j * H4;
    const float4* wh  = (const float4*)w_hh + (size_t)j * H4;

    float a0 = 0.f, a1 = 0.f, a2 = 0.f, a3 = 0.f;
    #pragma unroll
    for (int k = lane; k < H4; k += 32) {
        float4 xv = x4[k];
        float4 hv = h4[k];
        a0 += dot4(wi[k            ], xv) + dot4(wh[k            ], hv);
        a1 += dot4(wi[k +     GATE4], xv) + dot4(wh[k +     GATE4], hv);
        a2 += dot4(wi[k + 2 * GATE4], xv) + dot4(wh[k + 2 * GATE4], hv);
        a3 += dot4(wi[k + 3 * GATE4], xv) + dot4(wh[k + 3 * GATE4], hv);
    }
    a0 = warpSum(a0); a1 = warpSum(a1); a2 = warpSum(a2); a3 = warpSum(a3);
    if (lane == 0) {
        float gi = a0 + b_ih[j        ] + b_hh[j        ];
        float gf = a1 + b_ih[j +     H] + b_hh[j +     H];
        float gg = a2 + b_ih[j + 2 * H] + b_hh[j + 2 * H];
        float go = a3 + b_ih[j + 3 * H] + b_hh[j + 3 * H];
        float c  = sigm(gf) * cprev[j] + sigm(gi) * tanhf(gg);
        float h  = sigm(go) * tanhf(c);
        c_out[j] = c;
        h_out[j] = h;
    }
}

// ---------------- attention fc1: warp per row (512 rows x 1024) ----------------
__global__ void att_fc1_kernel(const float* __restrict__ Wmat,
                               const float* __restrict__ ht,
                               const float* __restrict__ b)
{
    int r    = (blockIdx.x * blockDim.x + threadIdx.x) >> 5;   // 0..511
    int lane = threadIdx.x & 31;
    const float4* w4 = (const float4*)Wmat + (size_t)r * H4;
    const float4* h4 = (const float4*)ht;
    float acc = 0.f;
    #pragma unroll
    for (int k = lane; k < H4; k += 32) acc += dot4(w4[k], h4[k]);
    acc = warpSum(acc);
    if (lane == 0) g_t1[r] = tanhf(acc + b[r]);
}

// ---------------- p, window bounds (1 block, 256 threads) ----------------
__global__ void p_kernel(const float* __restrict__ w2,
                         const float* __restrict__ b2, float Sf)
{
    __shared__ float sm[8];
    int t = threadIdx.x, lane = t & 31, wid = t >> 5;
    float acc = 0.f;
    for (int i = t; i < H2; i += 256) acc += g_t1[i] * w2[i];
    acc = warpSum(acc);
    if (lane == 0) sm[wid] = acc;
    __syncthreads();
    if (t == 0) {
        float s = b2[0];
        #pragma unroll
        for (int i = 0; i < 8; i++) s += sm[i];
        float p = Sf * sigm(s);
        g_p  = p;
        g_ws = (int)rintf(fmaxf(p - (float)WWIN, 0.f));
        g_we = (int)rintf(fminf(p + (float)WWIN, Sf - 1.f));
    }
}

// ---------------- scores: one block per window position ----------------
__global__ void scores_kernel(const float* __restrict__ enc,
                              const float* __restrict__ ht, int S)
{
    __shared__ float sm[8];
    int b = blockIdx.x;                    // 0..WIN-1
    int t = threadIdx.x, lane = t & 31, wid = t >> 5;
    int idx = g_ws + b;
    int ic  = min(max(idx, 0), S - 1);
    const float4* e4 = (const float4*)(enc + (size_t)ic * H);
    const float4* h4 = (const float4*)ht;
    float acc = dot4(e4[t], h4[t]);        // 256 threads cover 256 float4
    acc = warpSum(acc);
    if (lane == 0) sm[wid] = acc;
    __syncthreads();
    if (t == 0) {
        float s = 0.f;
        #pragma unroll
        for (int i = 0; i < 8; i++) s += sm[i];
        g_scores[b] = (idx <= g_we) ? s : -1e30f;
    }
}

// ---------------- softmax + gaussian over window (1 block, 256 thr) ----------------
__global__ void softmax_kernel(float* __restrict__ aout)
{
    __shared__ float sm[8];
    __shared__ float bc_max, bc_sum;
    int t = threadIdx.x, lane = t & 31, wid = t >> 5;
    float s = (t < WIN) ? g_scores[t] : -1e30f;

    float m = warpMax(s);
    if (lane == 0) sm[wid] = m;
    __syncthreads();
    if (t == 0) {
        float mm = sm[0];
        #pragma unroll
        for (int i = 1; i < 8; i++) mm = fmaxf(mm, sm[i]);
        bc_max = mm;
    }
    __syncthreads();
    float e = (t < WIN) ? expf(s - bc_max) : 0.f;
    float se = warpSum(e);
    __syncthreads();
    if (lane == 0) sm[wid] = se;
    __syncthreads();
    if (t == 0) {
        float ss = 0.f;
        #pragma unroll
        for (int i = 0; i < 8; i++) ss += sm[i];
        bc_sum = ss;
    }
    __syncthreads();
    if (t < WIN) {
        float a = e / bc_sum;
        int idx = g_ws + t;
        float g = expf(((float)idx - g_p) * (1.f / 2048.f));   // 2*STD_SQ = 2048
        aout[t] = (idx <= g_we) ? a * g : 0.f;
    }
}

// ---------------- ctx = a @ h_s (4 blocks x 256 threads, one thread per column) ----------------
__global__ void ctx_kernel(const float* __restrict__ enc,
                           const float* __restrict__ aout, int S)
{
    __shared__ float sa[WIN];
    __shared__ int   sic[WIN];
    int t = threadIdx.x;
    int ws = g_ws;
    for (int k = t; k < WIN; k += 256) {
        sa[k]  = aout[k];
        sic[k] = min(max(ws + k, 0), S - 1);
    }
    __syncthreads();
    int j = blockIdx.x * 256 + t;          // 0..1023
    float acc = 0.f;
    #pragma unroll 4
    for (int k = 0; k < WIN; k++)
        acc = fmaf(sa[k], enc[(size_t)sic[k] * H + j], acc);
    g_ctx[j] = acc;
}

// ---------------- fc1: warp per row over concat(ctx, h_t) (1024 x 2048) ----------------
__global__ void fc1_kernel(const float* __restrict__ Wmat,
                           const float* __restrict__ ht,
                           const float* __restrict__ b,
                           float* __restrict__ outv)
{
    int r    = (blockIdx.x * blockDim.x + threadIdx.x) >> 5;   // 0..1023
    int lane = threadIdx.x & 31;
    const float4* w4 = (const float4*)Wmat + (size_t)r * (2 * H4);
    const float4* c4 = (const float4*)g_ctx;
    const float4* h4 = (const float4*)ht;
    float acc = 0.f;
    #pragma unroll
    for (int k = lane; k < 2 * H4; k += 32) {
        float4 v = (k < H4) ? c4[k] : h4[k - H4];
        acc += dot4(w4[k], v);
    }
    acc = warpSum(acc);
    if (lane == 0) outv[r] = tanhf(acc + b[r]);
}

// ---------------- fc2: warp per row (32000 x 1024) -> raw logits ----------------
__global__ void fc2_kernel(const float* __restrict__ Wmat,
                           const float* __restrict__ xv,
                           const float* __restrict__ b,
                           float* __restrict__ y)
{
    int r    = (blockIdx.x * blockDim.x + threadIdx.x) >> 5;   // 0..31999
    int lane = threadIdx.x & 31;
    const float4* w4 = (const float4*)Wmat + (size_t)r * H4;
    const float4* x4 = (const float4*)xv;
    float acc = 0.f;
    #pragma unroll
    for (int k = lane; k < H4; k += 32) acc += dot4(w4[k], x4[k]);
    acc = warpSum(acc);
    if (lane == 0) y[r] = acc + b[r];
}

// ---------------- in-place log-softmax over V logits (1 block, 1024 thr) ----------------
__global__ void logsoftmax_kernel(float* __restrict__ y)
{
    __shared__ float sm[32];
    __shared__ float bc;
    int t = threadIdx.x, lane = t & 31, wid = t >> 5;

    float m = -1e30f;
    for (int i = t; i < V; i += 1024) m = fmaxf(m, y[i]);
    m = warpMax(m);
    if (lane == 0) sm[wid] = m;
    __syncthreads();
    if (t == 0) {
        float mm = sm[0];
        #pragma unroll
        for (int i = 1; i < 32; i++) mm = fmaxf(mm, sm[i]);
        bc = mm;
    }
    __syncthreads();
    float mx = bc;

    float se = 0.f;
    for (int i = t; i < V; i += 1024) se += expf(y[i] - mx);
    se = warpSum(se);
    __syncthreads();
    if (lane == 0) sm[wid] = se;
    __syncthreads();
    if (t == 0) {
        float ss = 0.f;
        #pragma unroll
        for (int i = 0; i < 32; i++) ss += sm[i];
        bc = mx + logf(ss);          // lse
    }
    __syncthreads();
    float lse = bc;
    for (int i = t; i < V; i += 1024) y[i] -= lse;
}

// ---------------- launch ----------------
extern "C" void kernel_launch(void* const* d_in, const int* in_sizes, int n_in,
                              void* d_out, int out_size)
{
    const float* enc  = (const float*)d_in[1];
    const int*   word = (const int*)  d_in[2];
    const float* h0   = (const float*)d_in[3];
    const float* c0   = (const float*)d_in[4];
    const float* emb  = (const float*)d_in[5];
    const float* wih  = (const float*)d_in[6];
    const float* whh  = (const float*)d_in[7];
    const float* bih  = (const float*)d_in[8];
    const float* bhh  = (const float*)d_in[9];
    const float* a1w  = (const float*)d_in[10];
    const float* a1b  = (const float*)d_in[11];
    const float* a2w  = (const float*)d_in[12];
    const float* a2b  = (const float*)d_in[13];
    const float* f1w  = (const float*)d_in[14];
    const float* f1b  = (const float*)d_in[15];
    const float* f2w  = (const float*)d_in[16];
    const float* f2b  = (const float*)d_in[17];

    int S = in_sizes[1] / H;     // encoder rows == source_sentence_length

    float* y    = (float*)d_out;            // [V]
    float* fco  = y   + V;                  // [H]   "out"
    float* hn   = fco + H;                  // [2,H]
    float* cn   = hn  + 2 * H;              // [2,H]
    float* aout = cn  + 2 * H;              // [WIN]

    // layer 0: x = embedding[word]
    lstm_kernel<<<128, 256>>>(emb, word, h0, c0, wih, whh, bih, bhh, hn, cn);
    // layer 1: x = h_new0
    lstm_kernel<<<128, 256>>>(hn, nullptr, h0 + H, c0 + H,
                              wih + 4 * H * H, whh + 4 * H * H,
                              bih + 4 * H, bhh + 4 * H, hn + H, cn + H);
    const float* ht = hn + H;

    att_fc1_kernel<<<64, 256>>>(a1w, ht, a1b);
    p_kernel<<<1, 256>>>(a2w, a2b, (float)S);
    scores_kernel<<<WIN, 256>>>(enc, ht, S);
    softmax_kernel<<<1, 256>>>(aout);
    ctx_kernel<<<4, 256>>>(enc, aout, S);
    fc1_kernel<<<128, 256>>>(f1w, ht, f1b, fco);
    fc2_kernel<<<V / 8, 256>>>(f2w, fco, f2b, y);
    logsoftmax_kernel<<<1, 1024>>>(y);
}

// round 2
// speedup vs baseline: 1.3653x; 1.3653x over previous
#include <cuda_runtime.h>
#include <math.h>

#define H      1024
#define H4     256            // float4 per H row
#define HH2    512
#define V      32000
#define WIN    129
#define NB     148
#define NT     1024
#define NWRP   (NB * 32)       // 4736 warps
#define SMAX   4096
#define NEG    -1e30f

// ---------------- persistent scratch (no allocation allowed) ----------------
__device__ float g_t1[HH2];          // tanh(att_fc1)
__device__ float g_sc[SMAX];         // full-sequence raw scores
__device__ float g_ctx[H];           // attention context (atomicAdd target)
__device__ unsigned g_cnt;           // barrier arrival counter
__device__ volatile unsigned g_sense;// barrier sense flag

// ---------------- helpers ----------------
__device__ __forceinline__ float dot4(float4 a, float4 b) {
    return fmaf(a.x, b.x, fmaf(a.y, b.y, fmaf(a.z, b.z, a.w * b.w)));
}
__device__ __forceinline__ float warpSum(float v) {
    #pragma unroll
    for (int o = 16; o > 0; o >>= 1) v += __shfl_xor_sync(0xffffffffu, v, o);
    return v;
}
__device__ __forceinline__ float warpMax(float v) {
    #pragma unroll
    for (int o = 16; o > 0; o >>= 1) v = fmaxf(v, __shfl_xor_sync(0xffffffffu, v, o));
    return v;
}
__device__ __forceinline__ float sigm(float x) { return 1.f / (1.f + expf(-x)); }

// ---------------- grid barrier (sense-reversing, all NB blocks) ----------------
__device__ __forceinline__ void gbar() {
    __syncthreads();
    if (threadIdx.x == 0) {
        unsigned my = g_sense;                 // volatile read
        __threadfence();                       // release prior writes
        if (atomicAdd(&g_cnt, 1u) == NB - 1u) {
            atomicExch(&g_cnt, 0u);            // reset for next barrier
            __threadfence();
            g_sense = my ^ 1u;                 // volatile store: release
        } else {
            while (g_sense == my) { }          // L2-bypassing volatile poll
            __threadfence();                   // acquire
        }
    }
    __syncthreads();
}

struct Shm {
    float gate[28];      // 7 rows x 4 gates
    float red[32];
    float sarr[WIN];
    float aarr[WIN];
    float p;
    int   ws, we;
    float mx, sum;
};

// ---------------- LSTM layer: 28 warps/block, 4 gate-warps per row ----------------
__device__ __forceinline__ void lstm_layer(
    const float4* __restrict__ x4, const float4* __restrict__ h4,
    const float* __restrict__ cprev,
    const float* __restrict__ wih, const float* __restrict__ whh,
    const float* __restrict__ bih, const float* __restrict__ bhh,
    float* __restrict__ hout, float* __restrict__ cout,
    int bid, int wid, int lane, Shm& sm)
{
    int q = wid >> 2;            // local row 0..7
    int gate = wid & 3;
    int r = bid * 7 + q;
    if (q < 7 && r < H) {
        const float4* wi = (const float4*)wih + ((size_t)gate * H + r) * H4;
        const float4* wh = (const float4*)whh + ((size_t)gate * H + r) * H4;
        float acc = 0.f;
        #pragma unroll
        for (int k = 0; k < 8; k++) {
            int i = lane + 32 * k;
            acc += dot4(wi[i], x4[i]) + dot4(wh[i], h4[i]);
        }
        acc = warpSum(acc);
        if (lane == 0) sm.gate[q * 4 + gate] = acc;
    }
    __syncthreads();
    int t = threadIdx.x;
    if (t < 7) {
        int r2 = bid * 7 + t;
        if (r2 < H) {
            float gi = sm.gate[t * 4 + 0] + bih[r2        ] + bhh[r2        ];
            float gf = sm.gate[t * 4 + 1] + bih[r2 +     H] + bhh[r2 +     H];
            float gg = sm.gate[t * 4 + 2] + bih[r2 + 2 * H] + bhh[r2 + 2 * H];
            float go = sm.gate[t * 4 + 3] + bih[r2 + 3 * H] + bhh[r2 + 3 * H];
            float c  = sigm(gf) * cprev[r2] + sigm(gi) * tanhf(gg);
            cout[r2] = c;
            hout[r2] = sigm(go) * tanhf(c);
        }
    }
}

// ---------------- the megakernel ----------------
__global__ void __launch_bounds__(NT, 1) decoder_mega(
    const float* __restrict__ enc, const int* __restrict__ word,
    const float* __restrict__ h0,  const float* __restrict__ c0,
    const float* __restrict__ emb,
    const float* __restrict__ wih, const float* __restrict__ whh,
    const float* __restrict__ bih, const float* __restrict__ bhh,
    const float* __restrict__ a1w, const float* __restrict__ a1b,
    const float* __restrict__ a2w, const float* __restrict__ a2b,
    const float* __restrict__ f1w, const float* __restrict__ f1b,
    const float* __restrict__ f2w, const float* __restrict__ f2b,
    float* __restrict__ dout, int S)
{
    __shared__ Shm sm;
    const int tid = threadIdx.x, lane = tid & 31, wid = tid >> 5;
    const int bid = blockIdx.x;
    const int gw  = bid * 32 + wid;
    const float Sf = (float)S;

    float* y    = dout;              // [V]
    float* fco  = y   + V;           // [H]
    float* hn   = fco + H;           // [2,H]
    float* cn   = hn  + 2 * H;       // [2,H]
    float* aout = cn  + 2 * H;       // [WIN]

    // ---- phase 0: LSTM layer 0 (x = embedding[word]) ----
    {
        const float4* x4 = (const float4*)(emb + (size_t)word[0] * H);
        const float4* h4 = (const float4*)h0;
        lstm_layer(x4, h4, c0, wih, whh, bih, bhh, hn, cn, bid, wid, lane, sm);
    }
    gbar();

    // ---- phase 1: LSTM layer 1 (x = h of layer 0) ----
    {
        const float4* x4 = (const float4*)hn;
        const float4* h4 = (const float4*)(h0 + H);
        lstm_layer(x4, h4, c0 + H, wih + 4 * H * H, whh + 4 * H * H,
                   bih + 4 * H, bhh + 4 * H, hn + H, cn + H, bid, wid, lane, sm);
    }
    gbar();

    const float* ht = hn + H;
    const float4* ht4 = (const float4*)ht;

    // ---- phase 2: att_fc1 (512 rows) + full-sequence scores + scratch reset ----
    if (gw < HH2) {
        const float4* w4 = (const float4*)a1w + (size_t)gw * H4;
        float acc = 0.f;
        #pragma unroll
        for (int k = 0; k < 8; k++) { int i = lane + 32 * k; acc += dot4(w4[i], ht4[i]); }
        acc = warpSum(acc);
        if (lane == 0) g_t1[gw] = tanhf(acc + a1b[gw]);
    } else {
        int s = gw - HH2;
        int slim = (S < SMAX) ? S : SMAX;
        if (s < slim) {
            const float4* e4 = (const float4*)(enc + (size_t)s * H);
            float acc = 0.f;
            #pragma unroll
            for (int k = 0; k < 8; k++) { int i = lane + 32 * k; acc += dot4(e4[i], ht4[i]); }
            acc = warpSum(acc);
            if (lane == 0) g_sc[s] = acc;
        }
    }
    if (bid == NB - 1) g_ctx[tid] = 0.f;   // blocks 144-147 idle in score range (S=4096)
    gbar();

    // ---- phase 3: redundant p + window softmax; distributed ctx ----
    {
        float part = (tid < HH2) ? g_t1[tid] * a2w[tid] : 0.f;
        part = warpSum(part);
        if (lane == 0) sm.red[wid] = part;
        __syncthreads();
        if (tid == 0) {
            float s = a2b[0];
            #pragma unroll
            for (int i = 0; i < 32; i++) s += sm.red[i];
            float p = Sf * sigm(s);
            sm.p  = p;
            sm.ws = (int)rintf(fmaxf(p - 64.f, 0.f));
            sm.we = (int)rintf(fminf(p + 64.f, Sf - 1.f));
        }
        __syncthreads();
        int ws = sm.ws, we = sm.we;
        if (tid < WIN) {
            int idx = ws + tid;
            int ic  = min(idx, S - 1);
            sm.sarr[tid] = (idx <= we) ? g_sc[ic] : NEG;
        }
        __syncthreads();
        if (tid < 32) {
            float m = NEG;
            for (int i = lane; i < WIN; i += 32) m = fmaxf(m, sm.sarr[i]);
            m = warpMax(m);
            float e = 0.f;
            for (int i = lane; i < WIN; i += 32) e += expf(sm.sarr[i] - m);
            e = warpSum(e);
            if (lane == 0) { sm.mx = m; sm.sum = e; }
        }
        __syncthreads();
        if (tid < WIN) {
            int idx = ws + tid;
            float a = expf(sm.sarr[tid] - sm.mx) / sm.sum;
            float gss = expf(((float)idx - sm.p) * (1.f / 2048.f));
            a = (idx <= we) ? a * gss : 0.f;
            sm.aarr[tid] = a;
            if (bid == 0) aout[tid] = a;
        }
        __syncthreads();
        if (bid < WIN) {                 // block b accumulates window row b
            float a = sm.aarr[bid];
            int idx = min(sm.ws + bid, S - 1);
            atomicAdd(&g_ctx[tid], a * enc[(size_t)idx * H + tid]);
        }
    }
    gbar();

    // ---- phase 4: fc1 (1024 rows x 2048), rows spread over all blocks ----
    {
        int r = wid * NB + bid;
        if (wid < 7 && r < H) {
            const float4* w4 = (const float4*)f1w + (size_t)r * (2 * H4);
            const float4* c4 = (const float4*)g_ctx;
            float acc = 0.f;
            #pragma unroll
            for (int k = 0; k < 8; k++) { int i = lane + 32 * k; acc += dot4(w4[i      ], c4[i]); }
            #pragma unroll
            for (int k = 0; k < 8; k++) { int i = lane + 32 * k; acc += dot4(w4[i + 256], ht4[i]); }
            acc = warpSum(acc);
            if (lane == 0) fco[r] = tanhf(acc + f1b[r]);
        }
    }
    gbar();

    // ---- phase 5: fc2 (32000 x 1024), all 4736 warps ----
    {
        const float4* x4 = (const float4*)fco;
        for (int r = gw; r < V; r += NWRP) {
            const float4* w4 = (const float4*)f2w + (size_t)r * H4;
            float acc = 0.f;
            #pragma unroll
            for (int k = 0; k < 8; k++) { int i = lane + 32 * k; acc += dot4(w4[i], x4[i]); }
            acc = warpSum(acc);
            if (lane == 0) y[r] = acc + f2b[r];
        }
    }
    gbar();

    // ---- phase 6: redundant log-softmax (deterministic, no atomics) ----
    {
        float m = NEG;
        for (int i = tid; i < V; i += NT) m = fmaxf(m, y[i]);
        m = warpMax(m);
        if (lane == 0) sm.red[wid] = m;
        __syncthreads();
        if (tid == 0) {
            float mm = sm.red[0];
            #pragma unroll
            for (int i = 1; i < 32; i++) mm = fmaxf(mm, sm.red[i]);
            sm.mx = mm;
        }
        __syncthreads();
        float mx = sm.mx;
        float e = 0.f;
        for (int i = tid; i < V; i += NT) e += expf(y[i] - mx);
        e = warpSum(e);
        __syncthreads();
        if (lane == 0) sm.red[wid] = e;
        __syncthreads();
        if (tid == 0) {
            float ss = 0.f;
            #pragma unroll
            for (int i = 0; i < 32; i++) ss += sm.red[i];
            sm.sum = mx + logf(ss);      // lse
        }
        __syncthreads();
        float lse = sm.sum;
        const int chunk = (V + NB - 1) / NB;          // 217
        int i = bid * chunk + tid;
        if (tid < chunk && i < V) y[i] -= lse;
    }
}

// ---------------- launch ----------------
extern "C" void kernel_launch(void* const* d_in, const int* in_sizes, int n_in,
                              void* d_out, int out_size)
{
    const float* enc  = (const float*)d_in[1];
    const int*   word = (const int*)  d_in[2];
    const float* h0   = (const float*)d_in[3];
    const float* c0   = (const float*)d_in[4];
    const float* emb  = (const float*)d_in[5];
    const float* wih  = (const float*)d_in[6];
    const float* whh  = (const float*)d_in[7];
    const float* bih  = (const float*)d_in[8];
    const float* bhh  = (const float*)d_in[9];
    const float* a1w  = (const float*)d_in[10];
    const float* a1b  = (const float*)d_in[11];
    const float* a2w  = (const float*)d_in[12];
    const float* a2b  = (const float*)d_in[13];
    const float* f1w  = (const float*)d_in[14];
    const float* f1b  = (const float*)d_in[15];
    const float* f2w  = (const float*)d_in[16];
    const float* f2b  = (const float*)d_in[17];

    int S = in_sizes[1] / H;

    decoder_mega<<<NB, NT>>>(enc, word, h0, c0, emb, wih, whh, bih, bhh,
                             a1w, a1b, a2w, a2b, f1w, f1b, f2w, f2b,
                             (float*)d_out, S);
}